// round 12
// baseline (speedup 1.0000x reference)
#include <cuda_runtime.h>
#include <math.h>

constexpr int NB = 64;
constexpr int NT = 12;
constexpr int ND = 256;
constexpr int NS = 512;
constexpr int NV = 512;
constexpr int GRAPH_STEPS = 3;

typedef unsigned long long ull;

// cross-kernel scratch
__device__ float g_part[2][2 * NB * NT];     // gate partial sums [colhalf][...]
__device__ ull   g_gs2T[512 * 32];           // [k][bpair] = (gsA, gsB)
__device__ ull   g_h2T[2 * 256 * 32];        // [br][col][bpair] = (hA, hB)

__device__ __forceinline__ float gelu_f(float x) {
    return 0.5f * x * (1.0f + erff(x * 0.70710678118654752440f));
}
__device__ __forceinline__ float sigmoid_f(float x) {
    return 1.0f / (1.0f + expf(-x));
}

// ---- packed f32x2 helpers (sm_103a) ----
__device__ __forceinline__ ull pk2(float lo, float hi) {
    ull r; asm("mov.b64 %0, {%1, %2};" : "=l"(r) : "f"(lo), "f"(hi)); return r;
}
__device__ __forceinline__ ull fma2(ull a, ull b, ull c) {
    ull d; asm("fma.rn.f32x2 %0, %1, %2, %3;" : "=l"(d) : "l"(a), "l"(b), "l"(c)); return d;
}
__device__ __forceinline__ ull add2(ull a, ull b) {
    ull d; asm("add.rn.f32x2 %0, %1, %2;" : "=l"(d) : "l"(a), "l"(b)); return d;
}
__device__ __forceinline__ float2 upk(ull v) {
    float2 f; asm("mov.b64 {%0, %1}, %2;" : "=f"(f.x), "=f"(f.y) : "l"(v)); return f;
}

// ---------------------------------------------------------------------------
// Kernel 1: gate MLPs, batch-pair packed (proven round-10 structure).
// grid = 128 = bpair(32) x gate(2) x colhalf(2), 1024 threads.
// ---------------------------------------------------------------------------
__global__ void __launch_bounds__(1024, 1)
k_gates(const float* __restrict__ evidence,
        const float* __restrict__ Wmg1, const float* __restrict__ bmg1,
        const float* __restrict__ Wmg2,
        const float* __restrict__ Wsg1, const float* __restrict__ bsg1,
        const float* __restrict__ Wsg2)
{
    __shared__ __align__(16) char ubuf[24576];   // ev2 (24KB) then comb slots
    __shared__ float red[2][NT][4];

    const int bid = blockIdx.x;
    const int p  = bid >> 2;          // batch pair
    const int g  = (bid >> 1) & 1;    // gate
    const int ch = bid & 1;           // col half
    const int bA = 2 * p, bB = 2 * p + 1;
    const int tid = threadIdx.x;

    const float* __restrict__ W1 = g ? Wsg1 : Wmg1;
    const float* __restrict__ B1 = g ? bsg1 : bmg1;
    const float* __restrict__ W2 = g ? Wsg2 : Wmg2;

    // pack evidence for both batches: ev2[k][r] = (evA[r][k], evB[r][k])
    ull* ev2 = (ull*)ubuf;
    {
        const int k = tid & 255, q = tid >> 8;
        #pragma unroll
        for (int r = q * 3; r < q * 3 + 3; r++)
            ev2[k * NT + r] = pk2(evidence[(bA * NT + r) * ND + k],
                                  evidence[(bB * NT + r) * ND + k]);
    }
    __syncthreads();

    const int jp = tid & 127;
    const int kg = tid >> 7;          // 0..7
    const int j  = ch * 128 + jp;

    ull acc[NT];
    #pragma unroll
    for (int i = 0; i < NT; i++) acc[i] = 0ull;
    {
        const int k0 = kg * 32;
        #pragma unroll 8
        for (int kk = 0; kk < 32; kk++) {
            const int k = k0 + kk;
            const float w = W1[k * ND + j];
            const ull wp = pk2(w, w);
            const ulonglong2* xp = (const ulonglong2*)(ev2 + k * NT);
            {
                const ulonglong2 q0 = xp[0], q1 = xp[1], q2 = xp[2];
                acc[0] = fma2(q0.x, wp, acc[0]);
                acc[1] = fma2(q0.y, wp, acc[1]);
                acc[2] = fma2(q1.x, wp, acc[2]);
                acc[3] = fma2(q1.y, wp, acc[3]);
                acc[4] = fma2(q2.x, wp, acc[4]);
                acc[5] = fma2(q2.y, wp, acc[5]);
            }
            {
                const ulonglong2 q3 = xp[3], q4 = xp[4], q5 = xp[5];
                acc[6]  = fma2(q3.x, wp, acc[6]);
                acc[7]  = fma2(q3.y, wp, acc[7]);
                acc[8]  = fma2(q4.x, wp, acc[8]);
                acc[9]  = fma2(q4.y, wp, acc[9]);
                acc[10] = fma2(q5.x, wp, acc[10]);
                acc[11] = fma2(q5.y, wp, acc[11]);
            }
        }
    }
    __syncthreads();   // ev2 reads done; ubuf becomes combine slots

    ull (*comb)[NT][128] = (ull (*)[NT][128])ubuf;   // [2 slots][12][128] = 24KB

    if (kg == 4 || kg == 5) {
        #pragma unroll
        for (int i = 0; i < NT; i++) comb[kg - 4][i][jp] = acc[i];
    }
    __syncthreads();
    if (kg == 0 || kg == 1) {
        #pragma unroll
        for (int i = 0; i < NT; i++) acc[i] = add2(acc[i], comb[kg][i][jp]);
    }
    __syncthreads();
    if (kg == 6 || kg == 7) {
        #pragma unroll
        for (int i = 0; i < NT; i++) comb[kg - 6][i][jp] = acc[i];
    }
    __syncthreads();
    if (kg == 2 || kg == 3) {
        #pragma unroll
        for (int i = 0; i < NT; i++) acc[i] = add2(acc[i], comb[kg - 2][i][jp]);
    }
    __syncthreads();
    if (kg == 2 || kg == 3) {
        #pragma unroll
        for (int i = 0; i < NT; i++) comb[kg - 2][i][jp] = acc[i];
    }
    __syncthreads();
    if (kg == 0 || kg == 1) {
        #pragma unroll
        for (int i = 0; i < NT; i++) acc[i] = add2(acc[i], comb[kg][i][jp]);
    }
    __syncthreads();
    if (kg == 1) {
        #pragma unroll
        for (int i = 0; i < NT; i++) comb[0][i][jp] = acc[i];
    }
    __syncthreads();

    if (kg == 0) {
        #pragma unroll
        for (int i = 0; i < NT; i++) acc[i] = add2(acc[i], comb[0][i][jp]);

        const float b1 = B1[j];
        const float w2 = W2[j];
        const int lane = jp & 31, warp = jp >> 5;
        #pragma unroll
        for (int r = 0; r < NT; r++) {
            const float2 f = upk(acc[r]);
            float yA = gelu_f(f.x + b1) * w2;
            float yB = gelu_f(f.y + b1) * w2;
            #pragma unroll
            for (int off = 16; off > 0; off >>= 1) {
                yA += __shfl_xor_sync(0xffffffffu, yA, off);
                yB += __shfl_xor_sync(0xffffffffu, yB, off);
            }
            if (lane == 0) { red[0][r][warp] = yA; red[1][r][warp] = yB; }
        }
    }
    __syncthreads();

    if (tid < 24) {
        const int bsel = tid / NT, t = tid % NT;
        const float s = red[bsel][t][0] + red[bsel][t][1] + red[bsel][t][2] + red[bsel][t][3];
        g_part[ch][(g * NB + (2 * p + bsel)) * NT + t] = s;
    }
}

// ---------------------------------------------------------------------------
// Kernel 2: sparse graph phase, one bpair per block.  grid = 32, 512 threads.
// Writes g_gs2T[k][p] = (gsA, gsB).
// ---------------------------------------------------------------------------
__global__ void __launch_bounds__(512, 2)
k_graph(const int* __restrict__ em,  const int* __restrict__ si,
        const int* __restrict__ sv,  const int* __restrict__ tsi,
        const int* __restrict__ tsv, const int* __restrict__ tvi,
        const int* __restrict__ tvv, const int* __restrict__ qi,
        const int* __restrict__ qv,
        const float* __restrict__ symbol_emb,
        const float* __restrict__ value_emb,
        const float* __restrict__ bmg2, const float* __restrict__ bsg2)
{
    __shared__ float walk[2][NS], nwalk[2][NS], wsum[2][NS], vw[2][NV];
    __shared__ float gate_s[2][2][NT];
    __shared__ int   e_msrc[2][NT], e_mtgt[2][NT], e_stgt[2][NT];
    __shared__ float e_mval[2][NT], e_sval[2][NT];
    __shared__ int   scand[2][16], vcand[2][16];
    __shared__ int   n_scand[2], n_vcand[2];

    const int p   = blockIdx.x;
    const int bA  = 2 * p;
    const int tid = threadIdx.x;

    // zero walk/wsum/vw (flat)
    {
        float* w0 = &walk[0][0];
        float* w1 = &wsum[0][0];
        float* w2 = &vw[0][0];
        w0[tid] = 0.f; w0[tid + 512] = 0.f;
        w1[tid] = 0.f; w1[tid + 512] = 0.f;
        w2[tid] = 0.f; w2[tid + 512] = 0.f;
    }
    if (tid < 48) {
        const int gg = tid / 24, rem = tid % 24;
        const int bsel = rem / NT, t = rem % NT;
        const int b = bA + bsel;
        const float b2 = gg ? bsg2[0] : bmg2[0];
        gate_s[gg][bsel][t] = sigmoid_f(g_part[0][(gg * NB + b) * NT + t]
                                      + g_part[1][(gg * NB + b) * NT + t] + b2);
    }
    if (tid >= 64 && tid < 88) {
        const int u = tid - 64;
        const int bsel = u / NT, t = u % NT;
        const int b = bA + bsel;
        const int mk  = em [b * NT + t];
        const int src = si [b * NT + t];
        const int svv = sv [b * NT + t];
        const int ts  = tsi[b * NT + t];
        const int tsx = tsv[b * NT + t];
        const int tv  = tvi[b * NT + t];
        const int tvx = tvv[b * NT + t];
        const int src_c = min(max(src, 0), NS - 1);
        const int ts_c  = min(max(ts,  0), NS - 1);
        const int tv_c  = min(max(tv,  0), NV - 1);
        const bool mm = ((mk == 0) || (mk == 1)) && (svv > 0) && (tvx > 0);
        const bool sm = (mk == 2) && (svv > 0) && (tsx > 0);
        e_msrc[bsel][t] = src_c; e_mtgt[bsel][t] = tv_c; e_mval[bsel][t] = mm ? 1.f : 0.f;
        e_stgt[bsel][t] = ts_c;  e_sval[bsel][t] = sm ? 1.f : 0.f;
    }
    __syncthreads();

    // warp-parallel dedup: warp0/1 = scand A/B, warp2/3 = vcand A/B
    if (tid < 128) {
        const int w = tid >> 5, lane = tid & 31;
        const int bsel = w & 1;
        const bool is_s = (w < 2);
        const int b = bA + bsel;
        int cand = 0x10000 + lane;
        bool active = false;
        if (is_s) {
            if (lane == 0) {
                const int q = min(max(qi[b], 0), NS - 1);
                cand = q; active = true;
                if (qv[b] > 0) walk[bsel][q] = 1.0f;
            } else if (lane < 13) {
                cand = e_stgt[bsel][lane - 1]; active = true;
            }
        } else {
            if (lane < 12) { cand = e_mtgt[bsel][lane]; active = true; }
        }
        const unsigned m = __match_any_sync(0xffffffffu, cand);
        const bool keep = active && ((m & ((1u << lane) - 1u)) == 0u);
        const unsigned keepmask = __ballot_sync(0xffffffffu, keep);
        if (keep) {
            const int idx = __popc(keepmask & ((1u << lane) - 1u));
            if (is_s) scand[bsel][idx] = cand; else vcand[bsel][idx] = cand;
        }
        if (lane == 0) {
            if (is_s) n_scand[bsel] = __popc(keepmask);
            else      n_vcand[bsel] = __popc(keepmask);
        }
    }
    if (tid >= 128 && tid < 152) {
        const int u = tid - 128;
        const int bsel = u / NT, t = u % NT;
        e_mval[bsel][t] *= gate_s[0][bsel][t];
        e_sval[bsel][t] *= gate_s[1][bsel][t];
    }
    __syncthreads();

    // walk evolution: warp 0 = batch A, warp 1 = batch B
    if (tid < 64) {
        const int w = tid >> 5;
        const int lane = tid & 31;
        const int nsc = n_scand[w];
        for (int iter = 0; iter <= GRAPH_STEPS; iter++) {
            if (lane < nsc) wsum[w][scand[w][lane]] += walk[w][scand[w][lane]];
            if (lane < NT) {
                const float c = walk[w][e_msrc[w][lane]] * e_mval[w][lane];
                if (c != 0.f) atomicAdd(&vw[w][e_mtgt[w][lane]], c);
            }
            __syncwarp();
            if (iter < GRAPH_STEPS) {
                if (lane < nsc) nwalk[w][scand[w][lane]] = 0.f;
                __syncwarp();
                if (lane < NT) {
                    const float c = walk[w][e_msrc[w][lane]] * e_sval[w][lane];
                    if (c != 0.f) atomicAdd(&nwalk[w][e_stgt[w][lane]], c);
                }
                __syncwarp();
                if (lane < nsc) walk[w][scand[w][lane]] = nwalk[w][scand[w][lane]];
                __syncwarp();
            }
        }
    }
    __syncthreads();

    // sparse gather -> g_gs2T[k][p] = (gsA, gsB)
    {
        float rA, rB;
        if (tid < 256) {
            const int d = tid;
            float a0 = 0.f, a1 = 0.f;
            const int n0 = n_scand[0], n1 = n_scand[1];
            for (int c = 0; c < n0; c++) {
                const int s = scand[0][c];
                a0 = fmaf(wsum[0][s], symbol_emb[s * ND + d], a0);
            }
            for (int c = 0; c < n1; c++) {
                const int s = scand[1][c];
                a1 = fmaf(wsum[1][s], symbol_emb[s * ND + d], a1);
            }
            rA = a0; rB = a1;
        } else {
            const int d = tid - 256;
            float a0 = 0.f, a1 = 0.f;
            const int n0 = n_vcand[0], n1 = n_vcand[1];
            for (int c = 0; c < n0; c++) {
                const int v = vcand[0][c];
                a0 = fmaf(vw[0][v], value_emb[v * ND + d], a0);
            }
            for (int c = 0; c < n1; c++) {
                const int v = vcand[1][c];
                a1 = fmaf(vw[1][v], value_emb[v * ND + d], a1);
            }
            rA = a0; rB = a1;
        }
        g_gs2T[tid * 32 + p] = pk2(rA, rB);
    }
}

// ---------------------------------------------------------------------------
// Kernel 3: layer-1 batch-shared GEMM + gelu.
// grid = 64 = br(2) x coltile(32, 8 cols).  1024 threads = kg(8) x cp(4) x bp(32).
// Weight loads warp-uniform (1 sector); activation loads 256B coalesced.
// ---------------------------------------------------------------------------
__global__ void __launch_bounds__(1024, 1)
k_l1(const float* __restrict__ Wf1, const float* __restrict__ bf1,
     const float* __restrict__ Wo1, const float* __restrict__ bo1)
{
    __shared__ ull comb[2048];    // [kg][cp][bp][pay] = 8*4*32*2

    const int bid = blockIdx.x;
    const int br  = bid >> 5;
    const int ct  = bid & 31;
    const int tid = threadIdx.x;
    const int kg  = tid >> 7;
    const int cp  = (tid >> 5) & 3;
    const int bp  = tid & 31;

    const float* __restrict__ W1 = br ? Wo1 : Wf1;
    const float* __restrict__ B1 = br ? bo1 : bf1;
    const int j0 = ct * 8 + 2 * cp;

    ull a0 = 0ull, a1 = 0ull;
    const int k0 = kg * 64;
    #pragma unroll 16
    for (int kk = 0; kk < 64; kk++) {
        const int k = k0 + kk;
        const float2 w = *(const float2*)&W1[k * ND + j0];   // warp-uniform
        const ull av = g_gs2T[k * 32 + bp];                  // coalesced
        a0 = fma2(av, pk2(w.x, w.x), a0);
        a1 = fma2(av, pk2(w.y, w.y), a1);
    }
    comb[((kg * 4 + cp) * 32 + bp) * 2 + 0] = a0;
    comb[((kg * 4 + cp) * 32 + bp) * 2 + 1] = a1;
    __syncthreads();

    if (tid < 256) {
        const int bp2 = tid & 31, pay = (tid >> 5) & 1, cp2 = tid >> 6;
        ull s = comb[((0 * 4 + cp2) * 32 + bp2) * 2 + pay];
        #pragma unroll
        for (int kg2 = 1; kg2 < 8; kg2++)
            s = add2(s, comb[((kg2 * 4 + cp2) * 32 + bp2) * 2 + pay]);
        const int col = ct * 8 + 2 * cp2 + pay;
        const float2 f = upk(s);
        const float bb = B1[col];
        g_h2T[(br * 256 + col) * 32 + bp2] = pk2(gelu_f(f.x + bb), gelu_f(f.y + bb));
    }
}

// ---------------------------------------------------------------------------
// Kernel 4: layer-2 batch-shared GEMMs + bias -> out (single writer, no atomics).
// grid = 96: blocks 0..63 logits (8 cols each), 64..95 feedback (8 cols each).
// 1024 threads = kg(8) x cp(4) x bp(32); K = 256 (32 k per kg).
// ---------------------------------------------------------------------------
__global__ void __launch_bounds__(1024, 1)
k_l2(const float* __restrict__ Wf2, const float* __restrict__ bf2,
     const float* __restrict__ Wo2, const float* __restrict__ bo2,
     float* __restrict__ out)
{
    __shared__ ull comb[2048];

    const int bid = blockIdx.x;
    const int tid = threadIdx.x;
    const bool lg = (bid < 64);
    const int ct = lg ? bid : (bid - 64);
    const int kg  = tid >> 7;
    const int cp  = (tid >> 5) & 3;
    const int bp  = tid & 31;

    const float* __restrict__ W = lg ? Wo2 : Wf2;
    const float* __restrict__ B = lg ? bo2 : bf2;
    const int wstride = lg ? NV : ND;
    const int hb = lg ? 256 : 0;
    const int j0 = ct * 8 + 2 * cp;

    ull a0 = 0ull, a1 = 0ull;
    const int k0 = kg * 32;
    #pragma unroll 16
    for (int kk = 0; kk < 32; kk++) {
        const int k = k0 + kk;
        const float2 w = *(const float2*)&W[k * wstride + j0];   // warp-uniform
        const ull av = g_h2T[(hb + k) * 32 + bp];                // coalesced
        a0 = fma2(av, pk2(w.x, w.x), a0);
        a1 = fma2(av, pk2(w.y, w.y), a1);
    }
    comb[((kg * 4 + cp) * 32 + bp) * 2 + 0] = a0;
    comb[((kg * 4 + cp) * 32 + bp) * 2 + 1] = a1;
    __syncthreads();

    if (tid < 256) {
        const int bp2 = tid & 31, pay = (tid >> 5) & 1, cp2 = tid >> 6;
        ull s = comb[((0 * 4 + cp2) * 32 + bp2) * 2 + pay];
        #pragma unroll
        for (int kg2 = 1; kg2 < 8; kg2++)
            s = add2(s, comb[((kg2 * 4 + cp2) * 32 + bp2) * 2 + pay]);
        const int col = ct * 8 + 2 * cp2 + pay;
        const float2 f = upk(s);
        const float bb = B[col];
        const int bA = 2 * bp2;
        if (lg) {
            out[bA * NV + col]       = f.x + bb;
            out[(bA + 1) * NV + col] = f.y + bb;
        } else {
            out[NB * NV + bA * ND + col]       = f.x + bb;
            out[NB * NV + (bA + 1) * ND + col] = f.y + bb;
        }
    }
}

// ---------------------------------------------------------------------------
extern "C" void kernel_launch(void* const* d_in, const int* in_sizes, int n_in,
                              void* d_out, int out_size)
{
    const int*   event_marker       = (const int*)  d_in[0];
    const int*   source_idx         = (const int*)  d_in[1];
    const int*   source_valid       = (const int*)  d_in[2];
    const int*   target_symbol_idx  = (const int*)  d_in[3];
    const int*   target_symbol_vld  = (const int*)  d_in[4];
    const int*   target_value_idx   = (const int*)  d_in[5];
    const int*   target_value_vld   = (const int*)  d_in[6];
    const int*   query_idx          = (const int*)  d_in[7];
    const int*   query_valid        = (const int*)  d_in[8];
    const float* evidence           = (const float*)d_in[9];
    const float* symbol_emb         = (const float*)d_in[10];
    const float* value_emb          = (const float*)d_in[11];
    const float* Wmg1 = (const float*)d_in[12];
    const float* bmg1 = (const float*)d_in[13];
    const float* Wmg2 = (const float*)d_in[14];
    const float* bmg2 = (const float*)d_in[15];
    const float* Wsg1 = (const float*)d_in[16];
    const float* bsg1 = (const float*)d_in[17];
    const float* Wsg2 = (const float*)d_in[18];
    const float* bsg2 = (const float*)d_in[19];
    const float* Wf1  = (const float*)d_in[20];
    const float* bf1  = (const float*)d_in[21];
    const float* Wf2  = (const float*)d_in[22];
    const float* bf2  = (const float*)d_in[23];
    const float* Wo1  = (const float*)d_in[24];
    const float* bo1  = (const float*)d_in[25];
    const float* Wo2  = (const float*)d_in[26];
    const float* bo2  = (const float*)d_in[27];

    float* out = (float*)d_out;

    k_gates<<<128, 1024>>>(evidence, Wmg1, bmg1, Wmg2, Wsg1, bsg1, Wsg2);
    k_graph<<<32, 512>>>(event_marker, source_idx, source_valid,
                         target_symbol_idx, target_symbol_vld,
                         target_value_idx, target_value_vld,
                         query_idx, query_valid,
                         symbol_emb, value_emb, bmg2, bsg2);
    k_l1<<<64, 1024>>>(Wf1, bf1, Wo1, bo1);
    k_l2<<<96, 1024>>>(Wf2, bf2, Wo2, bo2, out);
}

// round 13
// speedup vs baseline: 1.0686x; 1.0686x over previous
#include <cuda_runtime.h>
#include <cooperative_groups.h>
#include <math.h>

namespace cg = cooperative_groups;

constexpr int NB = 64;
constexpr int NT = 12;
constexpr int ND = 256;
constexpr int NS = 512;
constexpr int NV = 512;
constexpr int GRAPH_STEPS = 3;

typedef unsigned long long ull;

// cross-phase scratch
__device__ float g_part[2][2 * NB * NT];     // gate partial sums [colhalf][...]
__device__ ull   g_gs2T[512 * 32];           // [k][bpair] = (gsA, gsB)
__device__ ull   g_h2T[2 * 256 * 32];        // [br][col][bpair] = (hA, hB)

__device__ __forceinline__ float gelu_f(float x) {
    return 0.5f * x * (1.0f + erff(x * 0.70710678118654752440f));
}
__device__ __forceinline__ float sigmoid_f(float x) {
    return 1.0f / (1.0f + expf(-x));
}
__device__ __forceinline__ ull pk2(float lo, float hi) {
    ull r; asm("mov.b64 %0, {%1, %2};" : "=l"(r) : "f"(lo), "f"(hi)); return r;
}
__device__ __forceinline__ ull fma2(ull a, ull b, ull c) {
    ull d; asm("fma.rn.f32x2 %0, %1, %2, %3;" : "=l"(d) : "l"(a), "l"(b), "l"(c)); return d;
}
__device__ __forceinline__ ull add2(ull a, ull b) {
    ull d; asm("add.rn.f32x2 %0, %1, %2;" : "=l"(d) : "l"(a), "l"(b)); return d;
}
__device__ __forceinline__ float2 upk(ull v) {
    float2 f; asm("mov.b64 {%0, %1}, %2;" : "=f"(f.x), "=f"(f.y) : "l"(v)); return f;
}

struct Params {
    const int *em, *si, *sv, *tsi, *tsv, *tvi, *tvv, *qi, *qv;
    const float *evidence, *symbol_emb, *value_emb;
    const float *Wmg1, *bmg1, *Wmg2, *bmg2;
    const float *Wsg1, *bsg1, *Wsg2, *bsg2;
    const float *Wf1, *bf1, *Wf2, *bf2;
    const float *Wo1, *bo1, *Wo2, *bo2;
    float *out;
};

// ---------------------------------------------------------------------------
// One cooperative kernel, 128 blocks x 1024 threads, 4 phases.
// ---------------------------------------------------------------------------
__global__ void __launch_bounds__(1024, 1)
k_all(Params P)
{
    cg::grid_group grid = cg::this_grid();

    __shared__ __align__(16) char SMU[24576];   // phase-local union buffer
    __shared__ float red[2][NT][4];
    __shared__ float gate_s[2][2][NT];
    __shared__ int   e_msrc[2][NT], e_mtgt[2][NT], e_stgt[2][NT];
    __shared__ float e_mval[2][NT], e_sval[2][NT];
    __shared__ int   scand[2][16], vcand[2][16];
    __shared__ int   n_scand[2], n_vcand[2];

    const int bid = blockIdx.x;
    const int tid = threadIdx.x;

    // ===================== Phase A: gate MLPs (128 blocks) =====================
    {
        const int p  = bid >> 2;          // batch pair
        const int g  = (bid >> 1) & 1;    // gate
        const int ch = bid & 1;           // col half
        const int bA = 2 * p, bB = 2 * p + 1;

        const float* __restrict__ W1 = g ? P.Wsg1 : P.Wmg1;
        const float* __restrict__ B1 = g ? P.bsg1 : P.bmg1;
        const float* __restrict__ W2 = g ? P.Wsg2 : P.Wmg2;

        ull* ev2 = (ull*)SMU;
        {
            const int k = tid & 255, q = tid >> 8;
            #pragma unroll
            for (int r = q * 3; r < q * 3 + 3; r++)
                ev2[k * NT + r] = pk2(P.evidence[(bA * NT + r) * ND + k],
                                      P.evidence[(bB * NT + r) * ND + k]);
        }
        __syncthreads();

        const int jp = tid & 127;
        const int kg = tid >> 7;          // 0..7
        const int j  = ch * 128 + jp;

        ull acc[NT];
        #pragma unroll
        for (int i = 0; i < NT; i++) acc[i] = 0ull;
        {
            const int k0 = kg * 32;
            #pragma unroll 8
            for (int kk = 0; kk < 32; kk++) {
                const int k = k0 + kk;
                const float w = W1[k * ND + j];
                const ull wp = pk2(w, w);
                const ulonglong2* xp = (const ulonglong2*)(ev2 + k * NT);
                {
                    const ulonglong2 q0 = xp[0], q1 = xp[1], q2 = xp[2];
                    acc[0] = fma2(q0.x, wp, acc[0]);
                    acc[1] = fma2(q0.y, wp, acc[1]);
                    acc[2] = fma2(q1.x, wp, acc[2]);
                    acc[3] = fma2(q1.y, wp, acc[3]);
                    acc[4] = fma2(q2.x, wp, acc[4]);
                    acc[5] = fma2(q2.y, wp, acc[5]);
                }
                {
                    const ulonglong2 q3 = xp[3], q4 = xp[4], q5 = xp[5];
                    acc[6]  = fma2(q3.x, wp, acc[6]);
                    acc[7]  = fma2(q3.y, wp, acc[7]);
                    acc[8]  = fma2(q4.x, wp, acc[8]);
                    acc[9]  = fma2(q4.y, wp, acc[9]);
                    acc[10] = fma2(q5.x, wp, acc[10]);
                    acc[11] = fma2(q5.y, wp, acc[11]);
                }
            }
        }
        __syncthreads();   // ev2 reads done; SMU becomes combine slots

        ull (*comb)[NT][128] = (ull (*)[NT][128])SMU;   // [2 slots][12][128]

        if (kg == 4 || kg == 5) {
            #pragma unroll
            for (int i = 0; i < NT; i++) comb[kg - 4][i][jp] = acc[i];
        }
        __syncthreads();
        if (kg == 0 || kg == 1) {
            #pragma unroll
            for (int i = 0; i < NT; i++) acc[i] = add2(acc[i], comb[kg][i][jp]);
        }
        __syncthreads();
        if (kg == 6 || kg == 7) {
            #pragma unroll
            for (int i = 0; i < NT; i++) comb[kg - 6][i][jp] = acc[i];
        }
        __syncthreads();
        if (kg == 2 || kg == 3) {
            #pragma unroll
            for (int i = 0; i < NT; i++) acc[i] = add2(acc[i], comb[kg - 2][i][jp]);
        }
        __syncthreads();
        if (kg == 2 || kg == 3) {
            #pragma unroll
            for (int i = 0; i < NT; i++) comb[kg - 2][i][jp] = acc[i];
        }
        __syncthreads();
        if (kg == 0 || kg == 1) {
            #pragma unroll
            for (int i = 0; i < NT; i++) acc[i] = add2(acc[i], comb[kg][i][jp]);
        }
        __syncthreads();
        if (kg == 1) {
            #pragma unroll
            for (int i = 0; i < NT; i++) comb[0][i][jp] = acc[i];
        }
        __syncthreads();

        if (kg == 0) {
            #pragma unroll
            for (int i = 0; i < NT; i++) acc[i] = add2(acc[i], comb[0][i][jp]);

            const float b1 = B1[j];
            const float w2 = W2[j];
            const int lane = jp & 31, warp = jp >> 5;
            #pragma unroll
            for (int r = 0; r < NT; r++) {
                const float2 f = upk(acc[r]);
                float yA = gelu_f(f.x + b1) * w2;
                float yB = gelu_f(f.y + b1) * w2;
                #pragma unroll
                for (int off = 16; off > 0; off >>= 1) {
                    yA += __shfl_xor_sync(0xffffffffu, yA, off);
                    yB += __shfl_xor_sync(0xffffffffu, yB, off);
                }
                if (lane == 0) { red[0][r][warp] = yA; red[1][r][warp] = yB; }
            }
        }
        __syncthreads();

        if (tid < 24) {
            const int bsel = tid / NT, t = tid % NT;
            const float s = red[bsel][t][0] + red[bsel][t][1] + red[bsel][t][2] + red[bsel][t][3];
            g_part[ch][(g * NB + (2 * p + bsel)) * NT + t] = s;
        }
    }
    grid.sync();

    // ===================== Phase B: sparse graph (blocks 0..31) =====================
    if (bid < 32) {
        const int p  = bid;
        const int bA = 2 * p;
        float* SMUf  = (float*)SMU;
        float* walk  = SMUf;              // [2][512]
        float* nwalk = SMUf + 1024;
        float* wsum  = SMUf + 2048;
        float* vwv   = SMUf + 3072;

        walk[tid] = 0.f;  wsum[tid] = 0.f;  vwv[tid] = 0.f;

        if (tid < 48) {
            const int gg = tid / 24, rem = tid % 24;
            const int bsel = rem / NT, t = rem % NT;
            const int b = bA + bsel;
            const float b2 = gg ? P.bsg2[0] : P.bmg2[0];
            gate_s[gg][bsel][t] = sigmoid_f(g_part[0][(gg * NB + b) * NT + t]
                                          + g_part[1][(gg * NB + b) * NT + t] + b2);
        }
        if (tid >= 64 && tid < 88) {
            const int u = tid - 64;
            const int bsel = u / NT, t = u % NT;
            const int b = bA + bsel;
            const int mk  = P.em [b * NT + t];
            const int src = P.si [b * NT + t];
            const int svv = P.sv [b * NT + t];
            const int ts  = P.tsi[b * NT + t];
            const int tsx = P.tsv[b * NT + t];
            const int tv  = P.tvi[b * NT + t];
            const int tvx = P.tvv[b * NT + t];
            const int src_c = min(max(src, 0), NS - 1);
            const int ts_c  = min(max(ts,  0), NS - 1);
            const int tv_c  = min(max(tv,  0), NV - 1);
            const bool mm = ((mk == 0) || (mk == 1)) && (svv > 0) && (tvx > 0);
            const bool sm = (mk == 2) && (svv > 0) && (tsx > 0);
            e_msrc[bsel][t] = src_c; e_mtgt[bsel][t] = tv_c; e_mval[bsel][t] = mm ? 1.f : 0.f;
            e_stgt[bsel][t] = ts_c;  e_sval[bsel][t] = sm ? 1.f : 0.f;
        }
        __syncthreads();

        // warp-parallel dedup: warp0/1 = scand A/B, warp2/3 = vcand A/B
        if (tid < 128) {
            const int w = tid >> 5, lane = tid & 31;
            const int bsel = w & 1;
            const bool is_s = (w < 2);
            const int b = bA + bsel;
            int cand = 0x10000 + lane;
            bool active = false;
            if (is_s) {
                if (lane == 0) {
                    const int q = min(max(P.qi[b], 0), NS - 1);
                    cand = q; active = true;
                    if (P.qv[b] > 0) walk[bsel * NS + q] = 1.0f;
                } else if (lane < 13) {
                    cand = e_stgt[bsel][lane - 1]; active = true;
                }
            } else {
                if (lane < 12) { cand = e_mtgt[bsel][lane]; active = true; }
            }
            const unsigned m = __match_any_sync(0xffffffffu, cand);
            const bool keep = active && ((m & ((1u << lane) - 1u)) == 0u);
            const unsigned keepmask = __ballot_sync(0xffffffffu, keep);
            if (keep) {
                const int idx = __popc(keepmask & ((1u << lane) - 1u));
                if (is_s) scand[bsel][idx] = cand; else vcand[bsel][idx] = cand;
            }
            if (lane == 0) {
                if (is_s) n_scand[bsel] = __popc(keepmask);
                else      n_vcand[bsel] = __popc(keepmask);
            }
        }
        if (tid >= 128 && tid < 152) {
            const int u = tid - 128;
            const int bsel = u / NT, t = u % NT;
            e_mval[bsel][t] *= gate_s[0][bsel][t];
            e_sval[bsel][t] *= gate_s[1][bsel][t];
        }
        __syncthreads();

        // walk evolution: warp 0 = batch A, warp 1 = batch B
        if (tid < 64) {
            const int w = tid >> 5;
            const int lane = tid & 31;
            float* wk = walk + w * NS;
            float* nw = nwalk + w * NS;
            float* ws = wsum + w * NS;
            float* vv = vwv + w * NS;
            const int nsc = n_scand[w];
            for (int iter = 0; iter <= GRAPH_STEPS; iter++) {
                if (lane < nsc) ws[scand[w][lane]] += wk[scand[w][lane]];
                if (lane < NT) {
                    const float c = wk[e_msrc[w][lane]] * e_mval[w][lane];
                    if (c != 0.f) atomicAdd(&vv[e_mtgt[w][lane]], c);
                }
                __syncwarp();
                if (iter < GRAPH_STEPS) {
                    if (lane < nsc) nw[scand[w][lane]] = 0.f;
                    __syncwarp();
                    if (lane < NT) {
                        const float c = wk[e_msrc[w][lane]] * e_sval[w][lane];
                        if (c != 0.f) atomicAdd(&nw[e_stgt[w][lane]], c);
                    }
                    __syncwarp();
                    if (lane < nsc) wk[scand[w][lane]] = nw[scand[w][lane]];
                    __syncwarp();
                }
            }
        }
        __syncthreads();

        // sparse gather -> g_gs2T[k][p] = (gsA, gsB)
        if (tid < 512) {
            float rA, rB;
            if (tid < 256) {
                const int d = tid;
                float a0 = 0.f, a1 = 0.f;
                const int n0 = n_scand[0], n1 = n_scand[1];
                for (int c = 0; c < n0; c++) {
                    const int s = scand[0][c];
                    a0 = fmaf(wsum[s], P.symbol_emb[s * ND + d], a0);
                }
                for (int c = 0; c < n1; c++) {
                    const int s = scand[1][c];
                    a1 = fmaf(wsum[NS + s], P.symbol_emb[s * ND + d], a1);
                }
                rA = a0; rB = a1;
            } else {
                const int d = tid - 256;
                float a0 = 0.f, a1 = 0.f;
                const int n0 = n_vcand[0], n1 = n_vcand[1];
                for (int c = 0; c < n0; c++) {
                    const int v = vcand[0][c];
                    a0 = fmaf(vwv[v], P.value_emb[v * ND + d], a0);
                }
                for (int c = 0; c < n1; c++) {
                    const int v = vcand[1][c];
                    a1 = fmaf(vwv[NS + v], P.value_emb[v * ND + d], a1);
                }
                rA = a0; rB = a1;
            }
            g_gs2T[tid * 32 + p] = pk2(rA, rB);
        }
    }
    grid.sync();

    // ===================== Phase C: layer-1 GEMM (128 blocks, 4 cols each) =====================
    {
        const int br = bid >> 6;
        const int ct = bid & 63;
        const int kg = tid >> 6;          // 0..15, 32 k each
        const int cp = (tid >> 5) & 1;    // 0..1
        const int bp = tid & 31;

        const float* __restrict__ W1 = br ? P.Wo1 : P.Wf1;
        const float* __restrict__ B1 = br ? P.bo1 : P.bf1;
        const int j0 = ct * 4 + 2 * cp;

        ull a0 = 0ull, a1 = 0ull;
        const int k0 = kg * 32;
        #pragma unroll 16
        for (int kk = 0; kk < 32; kk++) {
            const int k = k0 + kk;
            const float2 w = *(const float2*)&W1[k * ND + j0];   // warp-uniform
            const ull av = g_gs2T[k * 32 + bp];                  // coalesced
            a0 = fma2(av, pk2(w.x, w.x), a0);
            a1 = fma2(av, pk2(w.y, w.y), a1);
        }
        ull* comb = (ull*)SMU;   // [kg16][cp2][bp32][pay2] = 2048 ull
        comb[((kg * 2 + cp) * 32 + bp) * 2 + 0] = a0;
        comb[((kg * 2 + cp) * 32 + bp) * 2 + 1] = a1;
        __syncthreads();

        if (tid < 128) {
            const int bp2 = tid & 31, pay = (tid >> 5) & 1, cp2 = (tid >> 6) & 1;
            ull s = comb[((0 * 2 + cp2) * 32 + bp2) * 2 + pay];
            #pragma unroll
            for (int kg2 = 1; kg2 < 16; kg2++)
                s = add2(s, comb[((kg2 * 2 + cp2) * 32 + bp2) * 2 + pay]);
            const int col = ct * 4 + 2 * cp2 + pay;
            const float2 f = upk(s);
            const float bb = B1[col];
            g_h2T[(br * 256 + col) * 32 + bp2] = pk2(gelu_f(f.x + bb), gelu_f(f.y + bb));
        }
    }
    grid.sync();

    // ===================== Phase D: layer-2 GEMM (blocks 0..95, 8 cols each) =====================
    if (bid < 96) {
        const bool lg = (bid < 64);
        const int ct = lg ? bid : (bid - 64);
        const int kg = tid >> 7;          // 0..7
        const int cp = (tid >> 5) & 3;    // 0..3
        const int bp = tid & 31;

        const float* __restrict__ W = lg ? P.Wo2 : P.Wf2;
        const float* __restrict__ B = lg ? P.bo2 : P.bf2;
        const int wstride = lg ? NV : ND;
        const int hb = lg ? 256 : 0;
        const int j0 = ct * 8 + 2 * cp;

        ull a0 = 0ull, a1 = 0ull;
        const int k0 = kg * 32;
        #pragma unroll 16
        for (int kk = 0; kk < 32; kk++) {
            const int k = k0 + kk;
            const float2 w = *(const float2*)&W[k * wstride + j0];   // warp-uniform
            const ull av = g_h2T[(hb + k) * 32 + bp];                // coalesced
            a0 = fma2(av, pk2(w.x, w.x), a0);
            a1 = fma2(av, pk2(w.y, w.y), a1);
        }
        ull* comb = (ull*)SMU;
        comb[((kg * 4 + cp) * 32 + bp) * 2 + 0] = a0;
        comb[((kg * 4 + cp) * 32 + bp) * 2 + 1] = a1;
        __syncthreads();

        if (tid < 256) {
            const int bp2 = tid & 31, pay = (tid >> 5) & 1, cp2 = tid >> 6;
            ull s = comb[((0 * 4 + cp2) * 32 + bp2) * 2 + pay];
            #pragma unroll
            for (int kg2 = 1; kg2 < 8; kg2++)
                s = add2(s, comb[((kg2 * 4 + cp2) * 32 + bp2) * 2 + pay]);
            const int col = ct * 8 + 2 * cp2 + pay;
            const float2 f = upk(s);
            const float bb = B[col];
            const int bA = 2 * bp2;
            if (lg) {
                P.out[bA * NV + col]       = f.x + bb;
                P.out[(bA + 1) * NV + col] = f.y + bb;
            } else {
                P.out[NB * NV + bA * ND + col]       = f.x + bb;
                P.out[NB * NV + (bA + 1) * ND + col] = f.y + bb;
            }
        }
    }
}

// ---------------------------------------------------------------------------
extern "C" void kernel_launch(void* const* d_in, const int* in_sizes, int n_in,
                              void* d_out, int out_size)
{
    Params P;
    P.em  = (const int*)d_in[0];
    P.si  = (const int*)d_in[1];
    P.sv  = (const int*)d_in[2];
    P.tsi = (const int*)d_in[3];
    P.tsv = (const int*)d_in[4];
    P.tvi = (const int*)d_in[5];
    P.tvv = (const int*)d_in[6];
    P.qi  = (const int*)d_in[7];
    P.qv  = (const int*)d_in[8];
    P.evidence   = (const float*)d_in[9];
    P.symbol_emb = (const float*)d_in[10];
    P.value_emb  = (const float*)d_in[11];
    P.Wmg1 = (const float*)d_in[12];  P.bmg1 = (const float*)d_in[13];
    P.Wmg2 = (const float*)d_in[14];  P.bmg2 = (const float*)d_in[15];
    P.Wsg1 = (const float*)d_in[16];  P.bsg1 = (const float*)d_in[17];
    P.Wsg2 = (const float*)d_in[18];  P.bsg2 = (const float*)d_in[19];
    P.Wf1  = (const float*)d_in[20];  P.bf1  = (const float*)d_in[21];
    P.Wf2  = (const float*)d_in[22];  P.bf2  = (const float*)d_in[23];
    P.Wo1  = (const float*)d_in[24];  P.bo1  = (const float*)d_in[25];
    P.Wo2  = (const float*)d_in[26];  P.bo2  = (const float*)d_in[27];
    P.out  = (float*)d_out;

    cudaLaunchConfig_t cfg = {};
    cfg.gridDim  = dim3(128, 1, 1);
    cfg.blockDim = dim3(1024, 1, 1);
    cfg.dynamicSmemBytes = 0;
    cfg.stream = 0;
    cudaLaunchAttribute attrs[1];
    attrs[0].id = cudaLaunchAttributeCooperative;
    attrs[0].val.cooperative = 1;
    cfg.attrs = attrs;
    cfg.numAttrs = 1;
    cudaLaunchKernelEx(&cfg, k_all, P);
}

// round 14
// speedup vs baseline: 1.1485x; 1.0749x over previous
#include <cuda_runtime.h>
#include <cooperative_groups.h>
#include <math.h>

namespace cg = cooperative_groups;

constexpr int NB = 64;
constexpr int NT = 12;
constexpr int ND = 256;
constexpr int NS = 512;
constexpr int NV = 512;
constexpr int GRAPH_STEPS = 3;

typedef unsigned long long ull;

// cross-phase scratch
__device__ float g_part[2][2 * NB * NT];     // gate partial sums [colhalf][...]
__device__ ull   g_gs2T[512 * 32];           // [k][bpair] = (gsA, gsB)
__device__ ull   g_h2T[2 * 256 * 32];        // [br][col][bpair] = (hA, hB)

__device__ __forceinline__ float gelu_f(float x) {
    return 0.5f * x * (1.0f + erff(x * 0.70710678118654752440f));
}
__device__ __forceinline__ float sigmoid_f(float x) {
    return 1.0f / (1.0f + expf(-x));
}
__device__ __forceinline__ ull pk2(float lo, float hi) {
    ull r; asm("mov.b64 %0, {%1, %2};" : "=l"(r) : "f"(lo), "f"(hi)); return r;
}
__device__ __forceinline__ ull fma2(ull a, ull b, ull c) {
    ull d; asm("fma.rn.f32x2 %0, %1, %2, %3;" : "=l"(d) : "l"(a), "l"(b), "l"(c)); return d;
}
__device__ __forceinline__ ull add2(ull a, ull b) {
    ull d; asm("add.rn.f32x2 %0, %1, %2;" : "=l"(d) : "l"(a), "l"(b)); return d;
}
__device__ __forceinline__ float2 upk(ull v) {
    float2 f; asm("mov.b64 {%0, %1}, %2;" : "=f"(f.x), "=f"(f.y) : "l"(v)); return f;
}

struct Params {
    const int *em, *si, *sv, *tsi, *tsv, *tvi, *tvv, *qi, *qv;
    const float *evidence, *symbol_emb, *value_emb;
    const float *Wmg1, *bmg1, *Wmg2, *bmg2;
    const float *Wsg1, *bsg1, *Wsg2, *bsg2;
    const float *Wf1, *bf1, *Wf2, *bf2;
    const float *Wo1, *bo1, *Wo2, *bo2;
    float *out;
};

// ---------------------------------------------------------------------------
// One cooperative kernel, 128 blocks x 512 threads (128 regs/thread budget).
// ---------------------------------------------------------------------------
__global__ void __launch_bounds__(512, 1)
k_all(Params P)
{
    cg::grid_group grid = cg::this_grid();

    __shared__ __align__(16) char SMU[24576];   // phase-local union buffer
    __shared__ float red[2][NT][4];
    __shared__ float gate_s[2][2][NT];
    __shared__ int   e_msrc[2][NT], e_mtgt[2][NT], e_stgt[2][NT];
    __shared__ float e_mval[2][NT], e_sval[2][NT];
    __shared__ int   scand[2][16], vcand[2][16];
    __shared__ int   n_scand[2], n_vcand[2];

    const int bid = blockIdx.x;
    const int tid = threadIdx.x;

    // ===================== Phase A: gate MLPs (128 blocks) =====================
    {
        const int p  = bid >> 2;          // batch pair
        const int g  = (bid >> 1) & 1;    // gate
        const int ch = bid & 1;           // col half
        const int bA = 2 * p, bB = 2 * p + 1;

        const float* __restrict__ W1 = g ? P.Wsg1 : P.Wmg1;
        const float* __restrict__ B1 = g ? P.bsg1 : P.bmg1;
        const float* __restrict__ W2 = g ? P.Wsg2 : P.Wmg2;

        ull* ev2 = (ull*)SMU;
        {
            const int k = tid & 255, q = tid >> 8;   // q 0..1, 6 rows each
            #pragma unroll
            for (int r = q * 6; r < q * 6 + 6; r++)
                ev2[k * NT + r] = pk2(P.evidence[(bA * NT + r) * ND + k],
                                      P.evidence[(bB * NT + r) * ND + k]);
        }
        __syncthreads();

        const int jp = tid & 127;
        const int kg = tid >> 7;          // 0..3, 64 k each
        const int j  = ch * 128 + jp;

        ull acc[NT];
        #pragma unroll
        for (int i = 0; i < NT; i++) acc[i] = 0ull;
        {
            const int k0 = kg * 64;
            #pragma unroll 8
            for (int kk = 0; kk < 64; kk++) {
                const int k = k0 + kk;
                const float w = W1[k * ND + j];
                const ull wp = pk2(w, w);
                const ulonglong2* xp = (const ulonglong2*)(ev2 + k * NT);
                {
                    const ulonglong2 q0 = xp[0], q1 = xp[1], q2 = xp[2];
                    acc[0] = fma2(q0.x, wp, acc[0]);
                    acc[1] = fma2(q0.y, wp, acc[1]);
                    acc[2] = fma2(q1.x, wp, acc[2]);
                    acc[3] = fma2(q1.y, wp, acc[3]);
                    acc[4] = fma2(q2.x, wp, acc[4]);
                    acc[5] = fma2(q2.y, wp, acc[5]);
                }
                {
                    const ulonglong2 q3 = xp[3], q4 = xp[4], q5 = xp[5];
                    acc[6]  = fma2(q3.x, wp, acc[6]);
                    acc[7]  = fma2(q3.y, wp, acc[7]);
                    acc[8]  = fma2(q4.x, wp, acc[8]);
                    acc[9]  = fma2(q4.y, wp, acc[9]);
                    acc[10] = fma2(q5.x, wp, acc[10]);
                    acc[11] = fma2(q5.y, wp, acc[11]);
                }
            }
        }
        __syncthreads();   // ev2 reads done; SMU becomes combine slots

        ull (*comb)[NT][128] = (ull (*)[NT][128])SMU;   // [2 slots][12][128] = 24KB

        // combine 4 -> 1: kg2,3 store; kg0,1 add; kg1 store; kg0 add
        if (kg == 2 || kg == 3) {
            #pragma unroll
            for (int i = 0; i < NT; i++) comb[kg - 2][i][jp] = acc[i];
        }
        __syncthreads();
        if (kg == 0 || kg == 1) {
            #pragma unroll
            for (int i = 0; i < NT; i++) acc[i] = add2(acc[i], comb[kg][i][jp]);
        }
        __syncthreads();
        if (kg == 1) {
            #pragma unroll
            for (int i = 0; i < NT; i++) comb[0][i][jp] = acc[i];
        }
        __syncthreads();

        if (kg == 0) {
            #pragma unroll
            for (int i = 0; i < NT; i++) acc[i] = add2(acc[i], comb[0][i][jp]);

            const float b1 = B1[j];
            const float w2 = W2[j];
            const int lane = jp & 31, warp = jp >> 5;
            #pragma unroll
            for (int r = 0; r < NT; r++) {
                const float2 f = upk(acc[r]);
                float yA = gelu_f(f.x + b1) * w2;
                float yB = gelu_f(f.y + b1) * w2;
                #pragma unroll
                for (int off = 16; off > 0; off >>= 1) {
                    yA += __shfl_xor_sync(0xffffffffu, yA, off);
                    yB += __shfl_xor_sync(0xffffffffu, yB, off);
                }
                if (lane == 0) { red[0][r][warp] = yA; red[1][r][warp] = yB; }
            }
        }
        __syncthreads();

        if (tid < 24) {
            const int bsel = tid / NT, t = tid % NT;
            const float s = red[bsel][t][0] + red[bsel][t][1] + red[bsel][t][2] + red[bsel][t][3];
            g_part[ch][(g * NB + (2 * p + bsel)) * NT + t] = s;
        }
    }
    grid.sync();

    // ===================== Phase B: sparse graph (128 blocks = bpair x chunk4) =====================
    {
        const int p     = bid >> 2;
        const int chunk = bid & 3;
        const int bA    = 2 * p;
        float* SMUf  = (float*)SMU;
        float* walk  = SMUf;              // [2][512]
        float* nwalk = SMUf + 1024;
        float* wsum  = SMUf + 2048;
        float* vwv   = SMUf + 3072;

        walk[tid] = 0.f;  walk[tid + 512] = 0.f;
        wsum[tid] = 0.f;  wsum[tid + 512] = 0.f;
        vwv[tid]  = 0.f;  vwv[tid + 512]  = 0.f;

        if (tid < 48) {
            const int gg = tid / 24, rem = tid % 24;
            const int bsel = rem / NT, t = rem % NT;
            const int b = bA + bsel;
            const float b2 = gg ? P.bsg2[0] : P.bmg2[0];
            gate_s[gg][bsel][t] = sigmoid_f(g_part[0][(gg * NB + b) * NT + t]
                                          + g_part[1][(gg * NB + b) * NT + t] + b2);
        }
        if (tid >= 64 && tid < 88) {
            const int u = tid - 64;
            const int bsel = u / NT, t = u % NT;
            const int b = bA + bsel;
            const int mk  = P.em [b * NT + t];
            const int src = P.si [b * NT + t];
            const int svv = P.sv [b * NT + t];
            const int ts  = P.tsi[b * NT + t];
            const int tsx = P.tsv[b * NT + t];
            const int tv  = P.tvi[b * NT + t];
            const int tvx = P.tvv[b * NT + t];
            const int src_c = min(max(src, 0), NS - 1);
            const int ts_c  = min(max(ts,  0), NS - 1);
            const int tv_c  = min(max(tv,  0), NV - 1);
            const bool mm = ((mk == 0) || (mk == 1)) && (svv > 0) && (tvx > 0);
            const bool sm = (mk == 2) && (svv > 0) && (tsx > 0);
            e_msrc[bsel][t] = src_c; e_mtgt[bsel][t] = tv_c; e_mval[bsel][t] = mm ? 1.f : 0.f;
            e_stgt[bsel][t] = ts_c;  e_sval[bsel][t] = sm ? 1.f : 0.f;
        }
        __syncthreads();

        // warp-parallel dedup: warp0/1 = scand A/B, warp2/3 = vcand A/B
        if (tid < 128) {
            const int w = tid >> 5, lane = tid & 31;
            const int bsel = w & 1;
            const bool is_s = (w < 2);
            const int b = bA + bsel;
            int cand = 0x10000 + lane;
            bool active = false;
            if (is_s) {
                if (lane == 0) {
                    const int q = min(max(P.qi[b], 0), NS - 1);
                    cand = q; active = true;
                    if (P.qv[b] > 0) walk[bsel * NS + q] = 1.0f;
                } else if (lane < 13) {
                    cand = e_stgt[bsel][lane - 1]; active = true;
                }
            } else {
                if (lane < 12) { cand = e_mtgt[bsel][lane]; active = true; }
            }
            const unsigned m = __match_any_sync(0xffffffffu, cand);
            const bool keep = active && ((m & ((1u << lane) - 1u)) == 0u);
            const unsigned keepmask = __ballot_sync(0xffffffffu, keep);
            if (keep) {
                const int idx = __popc(keepmask & ((1u << lane) - 1u));
                if (is_s) scand[bsel][idx] = cand; else vcand[bsel][idx] = cand;
            }
            if (lane == 0) {
                if (is_s) n_scand[bsel] = __popc(keepmask);
                else      n_vcand[bsel] = __popc(keepmask);
            }
        }
        if (tid >= 128 && tid < 152) {
            const int u = tid - 128;
            const int bsel = u / NT, t = u % NT;
            e_mval[bsel][t] *= gate_s[0][bsel][t];
            e_sval[bsel][t] *= gate_s[1][bsel][t];
        }
        __syncthreads();

        // walk evolution: warp 0 = batch A, warp 1 = batch B (duplicated per chunk)
        if (tid < 64) {
            const int w = tid >> 5;
            const int lane = tid & 31;
            float* wk = walk + w * NS;
            float* nw = nwalk + w * NS;
            float* ws = wsum + w * NS;
            float* vv = vwv + w * NS;
            const int nsc = n_scand[w];
            for (int iter = 0; iter <= GRAPH_STEPS; iter++) {
                if (lane < nsc) ws[scand[w][lane]] += wk[scand[w][lane]];
                if (lane < NT) {
                    const float c = wk[e_msrc[w][lane]] * e_mval[w][lane];
                    if (c != 0.f) atomicAdd(&vv[e_mtgt[w][lane]], c);
                }
                __syncwarp();
                if (iter < GRAPH_STEPS) {
                    if (lane < nsc) nw[scand[w][lane]] = 0.f;
                    __syncwarp();
                    if (lane < NT) {
                        const float c = wk[e_msrc[w][lane]] * e_sval[w][lane];
                        if (c != 0.f) atomicAdd(&nw[e_stgt[w][lane]], c);
                    }
                    __syncwarp();
                    if (lane < nsc) wk[scand[w][lane]] = nw[scand[w][lane]];
                    __syncwarp();
                }
            }
        }
        __syncthreads();

        // sparse gather: this block's 128 entries -> g_gs2T[e][p]
        if (tid < 128) {
            const int e = chunk * 128 + tid;
            float rA, rB;
            if (e < 256) {
                const int d = e;
                float a0 = 0.f, a1 = 0.f;
                const int n0 = n_scand[0], n1 = n_scand[1];
                for (int c = 0; c < n0; c++) {
                    const int s = scand[0][c];
                    a0 = fmaf(wsum[s], P.symbol_emb[s * ND + d], a0);
                }
                for (int c = 0; c < n1; c++) {
                    const int s = scand[1][c];
                    a1 = fmaf(wsum[NS + s], P.symbol_emb[s * ND + d], a1);
                }
                rA = a0; rB = a1;
            } else {
                const int d = e - 256;
                float a0 = 0.f, a1 = 0.f;
                const int n0 = n_vcand[0], n1 = n_vcand[1];
                for (int c = 0; c < n0; c++) {
                    const int v = vcand[0][c];
                    a0 = fmaf(vwv[v], P.value_emb[v * ND + d], a0);
                }
                for (int c = 0; c < n1; c++) {
                    const int v = vcand[1][c];
                    a1 = fmaf(vwv[NS + v], P.value_emb[v * ND + d], a1);
                }
                rA = a0; rB = a1;
            }
            g_gs2T[e * 32 + p] = pk2(rA, rB);
        }
    }
    grid.sync();

    // ===================== Phase C: layer-1 GEMM (128 blocks, 4 cols each) =====================
    {
        const int br = bid >> 6;
        const int ct = bid & 63;
        const int kg = tid >> 6;          // 0..7, 64 k each
        const int cp = (tid >> 5) & 1;    // 0..1
        const int bp = tid & 31;

        const float* __restrict__ W1 = br ? P.Wo1 : P.Wf1;
        const float* __restrict__ B1 = br ? P.bo1 : P.bf1;
        const int j0 = ct * 4 + 2 * cp;

        ull a0 = 0ull, a1 = 0ull;
        const int k0 = kg * 64;
        #pragma unroll 16
        for (int kk = 0; kk < 64; kk++) {
            const int k = k0 + kk;
            const float2 w = *(const float2*)&W1[k * ND + j0];   // warp-uniform
            const ull av = g_gs2T[k * 32 + bp];                  // coalesced
            a0 = fma2(av, pk2(w.x, w.x), a0);
            a1 = fma2(av, pk2(w.y, w.y), a1);
        }
        ull* comb = (ull*)SMU;   // [kg8][cp2][bp32][pay2] = 1024 ull
        comb[((kg * 2 + cp) * 32 + bp) * 2 + 0] = a0;
        comb[((kg * 2 + cp) * 32 + bp) * 2 + 1] = a1;
        __syncthreads();

        if (tid < 128) {
            const int bp2 = tid & 31, pay = (tid >> 5) & 1, cp2 = (tid >> 6) & 1;
            ull s = comb[((0 * 2 + cp2) * 32 + bp2) * 2 + pay];
            #pragma unroll
            for (int kg2 = 1; kg2 < 8; kg2++)
                s = add2(s, comb[((kg2 * 2 + cp2) * 32 + bp2) * 2 + pay]);
            const int col = ct * 4 + 2 * cp2 + pay;
            const float2 f = upk(s);
            const float bb = B1[col];
            g_h2T[(br * 256 + col) * 32 + bp2] = pk2(gelu_f(f.x + bb), gelu_f(f.y + bb));
        }
    }
    grid.sync();

    // ===================== Phase D: layer-2 GEMM (128 blocks, 6 cols each) =====================
    {
        // concatenated output cols: [0,512) logits, [512,768) feedback
        const int kg = tid >> 7;          // 0..3, 64 k each
        const int rem = tid & 127;
        const int cp = rem >> 5;          // 0..3 (active < 3)
        const int bp = rem & 31;

        ull a0 = 0ull, a1 = 0ull;
        int col0 = 0;
        bool lg = true;
        if (cp < 3) {
            col0 = bid * 6 + 2 * cp;
            lg = (col0 < 512);
            const float* __restrict__ W = lg ? P.Wo2 : P.Wf2;
            const int wstride = lg ? NV : ND;
            const int hb = lg ? 256 : 0;
            const int jc = lg ? col0 : (col0 - 512);

            const int k0 = kg * 64;
            #pragma unroll 16
            for (int kk = 0; kk < 64; kk++) {
                const int k = k0 + kk;
                const float2 w = *(const float2*)&W[k * wstride + jc];   // warp-uniform
                const ull av = g_h2T[(hb + k) * 32 + bp];                // coalesced
                a0 = fma2(av, pk2(w.x, w.x), a0);
                a1 = fma2(av, pk2(w.y, w.y), a1);
            }
        }
        ull* comb = (ull*)SMU;   // [kg4][cp3][bp32][pay2] = 768 ull
        if (cp < 3) {
            comb[((kg * 3 + cp) * 32 + bp) * 2 + 0] = a0;
            comb[((kg * 3 + cp) * 32 + bp) * 2 + 1] = a1;
        }
        __syncthreads();

        if (tid < 192) {
            const int bp2 = tid & 31, pay = (tid >> 5) & 1, cp2 = tid >> 6;  // cp2 0..2
            ull s = comb[((0 * 3 + cp2) * 32 + bp2) * 2 + pay];
            #pragma unroll
            for (int kg2 = 1; kg2 < 4; kg2++)
                s = add2(s, comb[((kg2 * 3 + cp2) * 32 + bp2) * 2 + pay]);
            const int c0 = bid * 6 + 2 * cp2 + pay;
            const float2 f = upk(s);
            const int bA = 2 * bp2;
            if (c0 < 512) {
                const float bb = P.bo2[c0];
                P.out[bA * NV + c0]       = f.x + bb;
                P.out[(bA + 1) * NV + c0] = f.y + bb;
            } else {
                const int fc = c0 - 512;
                const float bb = P.bf2[fc];
                P.out[NB * NV + bA * ND + fc]       = f.x + bb;
                P.out[NB * NV + (bA + 1) * ND + fc] = f.y + bb;
            }
        }
    }
}

// ---------------------------------------------------------------------------
extern "C" void kernel_launch(void* const* d_in, const int* in_sizes, int n_in,
                              void* d_out, int out_size)
{
    Params P;
    P.em  = (const int*)d_in[0];
    P.si  = (const int*)d_in[1];
    P.sv  = (const int*)d_in[2];
    P.tsi = (const int*)d_in[3];
    P.tsv = (const int*)d_in[4];
    P.tvi = (const int*)d_in[5];
    P.tvv = (const int*)d_in[6];
    P.qi  = (const int*)d_in[7];
    P.qv  = (const int*)d_in[8];
    P.evidence   = (const float*)d_in[9];
    P.symbol_emb = (const float*)d_in[10];
    P.value_emb  = (const float*)d_in[11];
    P.Wmg1 = (const float*)d_in[12];  P.bmg1 = (const float*)d_in[13];
    P.Wmg2 = (const float*)d_in[14];  P.bmg2 = (const float*)d_in[15];
    P.Wsg1 = (const float*)d_in[16];  P.bsg1 = (const float*)d_in[17];
    P.Wsg2 = (const float*)d_in[18];  P.bsg2 = (const float*)d_in[19];
    P.Wf1  = (const float*)d_in[20];  P.bf1  = (const float*)d_in[21];
    P.Wf2  = (const float*)d_in[22];  P.bf2  = (const float*)d_in[23];
    P.Wo1  = (const float*)d_in[24];  P.bo1  = (const float*)d_in[25];
    P.Wo2  = (const float*)d_in[26];  P.bo2  = (const float*)d_in[27];
    P.out  = (float*)d_out;

    cudaLaunchConfig_t cfg = {};
    cfg.gridDim  = dim3(128, 1, 1);
    cfg.blockDim = dim3(512, 1, 1);
    cfg.dynamicSmemBytes = 0;
    cfg.stream = 0;
    cudaLaunchAttribute attrs[1];
    attrs[0].id = cudaLaunchAttributeCooperative;
    attrs[0].val.cooperative = 1;
    cfg.attrs = attrs;
    cfg.numAttrs = 1;
    cudaLaunchKernelEx(&cfg, k_all, P);
}

// round 15
// speedup vs baseline: 1.3489x; 1.1745x over previous
#include <cuda_runtime.h>
#include <math.h>

constexpr int NB = 64;
constexpr int NT = 12;
constexpr int ND = 256;
constexpr int NS = 512;
constexpr int NV = 512;
constexpr int GRAPH_STEPS = 3;

typedef unsigned long long ull;

// cross-kernel scratch: gate partial sums [colhalf][(g*NB+b)*NT+t]
__device__ float g_part[2][2 * NB * NT];

__device__ __forceinline__ float gelu_f(float x) {
    return 0.5f * x * (1.0f + erff(x * 0.70710678118654752440f));
}
__device__ __forceinline__ float sigmoid_f(float x) {
    return 1.0f / (1.0f + expf(-x));
}

// ---- packed f32x2 helpers (sm_103a) ----
__device__ __forceinline__ ull pk2(float lo, float hi) {
    ull r; asm("mov.b64 %0, {%1, %2};" : "=l"(r) : "f"(lo), "f"(hi)); return r;
}
__device__ __forceinline__ ull fma2(ull a, ull b, ull c) {
    ull d; asm("fma.rn.f32x2 %0, %1, %2, %3;" : "=l"(d) : "l"(a), "l"(b), "l"(c)); return d;
}
__device__ __forceinline__ ull add2(ull a, ull b) {
    ull d; asm("add.rn.f32x2 %0, %1, %2;" : "=l"(d) : "l"(a), "l"(b)); return d;
}
__device__ __forceinline__ float2 upk(ull v) {
    float2 f; asm("mov.b64 {%0, %1}, %2;" : "=f"(f.x), "=f"(f.y) : "l"(v)); return f;
}

// ---------------------------------------------------------------------------
// Kernel A: gate MLPs, batch-pair packed, SINGLE-SHOT K-combine.
// grid = 128 = bpair(32) x gate(2) x colhalf(2), 1024 threads.
// Dynamic smem (96KB): ev2 (24KB) during FMA loop, then comb[8][12][128] ull.
// Also zeroes the output buffer for kernel B's atomic accumulation.
// ---------------------------------------------------------------------------
__global__ void __launch_bounds__(1024, 1)
k_gates(const float* __restrict__ evidence,
        const float* __restrict__ Wmg1, const float* __restrict__ bmg1,
        const float* __restrict__ Wmg2,
        const float* __restrict__ Wsg1, const float* __restrict__ bsg1,
        const float* __restrict__ Wsg2,
        float* __restrict__ out)
{
    extern __shared__ __align__(16) char ubuf[];   // 96KB dynamic
    __shared__ float red[2][NT][4];

    const int bid = blockIdx.x;
    const int p  = bid >> 2;          // batch pair
    const int g  = (bid >> 1) & 1;    // gate
    const int ch = bid & 1;           // col half
    const int bA = 2 * p, bB = 2 * p + 1;
    const int tid = threadIdx.x;

    // zero out (48K floats / 128 blocks = 384 each) for kernel B atomics
    if (tid < 384) out[bid * 384 + tid] = 0.f;

    const float* __restrict__ W1 = g ? Wsg1 : Wmg1;
    const float* __restrict__ B1 = g ? bsg1 : bmg1;
    const float* __restrict__ W2 = g ? Wsg2 : Wmg2;

    // pack evidence for both batches: ev2[k][r] = (evA[r][k], evB[r][k])
    ull* ev2 = (ull*)ubuf;
    {
        const int k = tid & 255, q = tid >> 8;
        #pragma unroll
        for (int r = q * 3; r < q * 3 + 3; r++)
            ev2[k * NT + r] = pk2(evidence[(bA * NT + r) * ND + k],
                                  evidence[(bB * NT + r) * ND + k]);
    }
    __syncthreads();

    const int jp = tid & 127;
    const int kg = tid >> 7;          // 0..7
    const int j  = ch * 128 + jp;

    ull acc[NT];
    #pragma unroll
    for (int i = 0; i < NT; i++) acc[i] = 0ull;
    {
        const int k0 = kg * 32;
        #pragma unroll 8
        for (int kk = 0; kk < 32; kk++) {
            const int k = k0 + kk;
            const float w = W1[k * ND + j];
            const ull wp = pk2(w, w);
            const ulonglong2* xp = (const ulonglong2*)(ev2 + k * NT);
            {
                const ulonglong2 q0 = xp[0], q1 = xp[1], q2 = xp[2];
                acc[0] = fma2(q0.x, wp, acc[0]);
                acc[1] = fma2(q0.y, wp, acc[1]);
                acc[2] = fma2(q1.x, wp, acc[2]);
                acc[3] = fma2(q1.y, wp, acc[3]);
                acc[4] = fma2(q2.x, wp, acc[4]);
                acc[5] = fma2(q2.y, wp, acc[5]);
            }
            {
                const ulonglong2 q3 = xp[3], q4 = xp[4], q5 = xp[5];
                acc[6]  = fma2(q3.x, wp, acc[6]);
                acc[7]  = fma2(q3.y, wp, acc[7]);
                acc[8]  = fma2(q4.x, wp, acc[8]);
                acc[9]  = fma2(q4.y, wp, acc[9]);
                acc[10] = fma2(q5.x, wp, acc[10]);
                acc[11] = fma2(q5.y, wp, acc[11]);
            }
        }
    }
    __syncthreads();   // ev2 reads done; ubuf becomes comb[8][12][128]

    ull* comb = (ull*)ubuf;
    #pragma unroll
    for (int i = 0; i < NT; i++)
        comb[(kg * NT + i) * 128 + jp] = acc[i];
    __syncthreads();

    // single-shot reduction: 512 threads, each (rg, jp) handles 3 rows
    if (tid < 512) {
        const int jr = tid & 127;        // jp
        const int rg = tid >> 7;         // 0..3 -> rows 3rg..3rg+2
        const int jc = ch * 128 + jr;
        const float b1 = B1[jc];
        const float w2 = W2[jc];
        const int lane = tid & 31;
        const int ws   = (tid >> 5) & 3; // warp slot within rg
        #pragma unroll
        for (int rr = 0; rr < 3; rr++) {
            const int r = rg * 3 + rr;
            ull s = comb[(0 * NT + r) * 128 + jr];
            #pragma unroll
            for (int k2 = 1; k2 < 8; k2++)
                s = add2(s, comb[(k2 * NT + r) * 128 + jr]);
            const float2 f = upk(s);
            float yA = gelu_f(f.x + b1) * w2;
            float yB = gelu_f(f.y + b1) * w2;
            #pragma unroll
            for (int off = 16; off > 0; off >>= 1) {
                yA += __shfl_xor_sync(0xffffffffu, yA, off);
                yB += __shfl_xor_sync(0xffffffffu, yB, off);
            }
            if (lane == 0) { red[0][r][ws] = yA; red[1][r][ws] = yB; }
        }
    }
    __syncthreads();

    if (tid < 24) {
        const int bsel = tid / NT, t = tid % NT;
        const float s = red[bsel][t][0] + red[bsel][t][1] + red[bsel][t][2] + red[bsel][t][3];
        g_part[ch][(g * NB + (2 * p + bsel)) * NT + t] = s;
    }
}

// ---------------------------------------------------------------------------
// Kernel B: sparse graph + output MLPs, batch-pair packed (proven R10).
// grid = 128 = bpair(32) x branch(2) x colhalf(2), 1024 threads.
// ---------------------------------------------------------------------------
__global__ void __launch_bounds__(1024, 1)
k_graph_out(const int* __restrict__ em,  const int* __restrict__ si,
            const int* __restrict__ sv,  const int* __restrict__ tsi,
            const int* __restrict__ tsv, const int* __restrict__ tvi,
            const int* __restrict__ tvv, const int* __restrict__ qi,
            const int* __restrict__ qv,
            const float* __restrict__ symbol_emb,
            const float* __restrict__ value_emb,
            const float* __restrict__ bmg2, const float* __restrict__ bsg2,
            const float* __restrict__ Wf1, const float* __restrict__ bf1,
            const float* __restrict__ Wf2, const float* __restrict__ bf2,
            const float* __restrict__ Wo1, const float* __restrict__ bo1,
            const float* __restrict__ Wo2, const float* __restrict__ bo2,
            float* __restrict__ out)
{
    __shared__ __align__(16) char ubuf[16384];   // walk arrays, then comb slots
    __shared__ ull   gs2[2 * ND];                // 4KB  (gsA, gsB) per k
    __shared__ ull   h2[128];                    // 1KB  this block's h col-half
    __shared__ float gate_s[2][2][NT];
    __shared__ int   e_msrc[2][NT], e_mtgt[2][NT], e_stgt[2][NT];
    __shared__ float e_mval[2][NT], e_sval[2][NT];
    __shared__ int   scand[2][16], vcand[2][16];
    __shared__ int   n_scand[2], n_vcand[2];

    const int bid = blockIdx.x;
    const int p   = bid >> 2;
    const int br  = (bid >> 1) & 1;
    const int ch  = bid & 1;
    const int bA  = 2 * p;
    const int tid = threadIdx.x;

    float* walk  = (float*)ubuf;          // [2][512]
    float* nwalk = walk + 1024;
    float* wsum  = walk + 2048;
    float* vw    = walk + 3072;

    walk[tid] = 0.f;  wsum[tid] = 0.f;  vw[tid] = 0.f;

    // gate scalars for both gates x both batches
    if (tid < 48) {
        const int g = tid / 24, rem = tid % 24;
        const int bsel = rem / NT, t = rem % NT;
        const int b = bA + bsel;
        const float b2 = g ? bsg2[0] : bmg2[0];
        gate_s[g][bsel][t] = sigmoid_f(g_part[0][(g * NB + b) * NT + t]
                                     + g_part[1][(g * NB + b) * NT + t] + b2);
    }
    // edge indices + validity
    if (tid >= 64 && tid < 88) {
        const int u = tid - 64;
        const int bsel = u / NT, t = u % NT;
        const int b = bA + bsel;
        const int mk  = em [b * NT + t];
        const int src = si [b * NT + t];
        const int svv = sv [b * NT + t];
        const int ts  = tsi[b * NT + t];
        const int tsx = tsv[b * NT + t];
        const int tv  = tvi[b * NT + t];
        const int tvx = tvv[b * NT + t];
        const int src_c = min(max(src, 0), NS - 1);
        const int ts_c  = min(max(ts,  0), NS - 1);
        const int tv_c  = min(max(tv,  0), NV - 1);
        const bool mm = ((mk == 0) || (mk == 1)) && (svv > 0) && (tvx > 0);
        const bool sm = (mk == 2) && (svv > 0) && (tsx > 0);
        e_msrc[bsel][t] = src_c; e_mtgt[bsel][t] = tv_c; e_mval[bsel][t] = mm ? 1.f : 0.f;
        e_stgt[bsel][t] = ts_c;  e_sval[bsel][t] = sm ? 1.f : 0.f;
    }
    __syncthreads();

    // warp-parallel dedup: warp0/1 = scand A/B, warp2/3 = vcand A/B
    if (tid < 128) {
        const int w = tid >> 5, lane = tid & 31;
        const int bsel = w & 1;
        const bool is_s = (w < 2);
        const int b = bA + bsel;
        int cand = 0x10000 + lane;    // unique sentinel for inactive lanes
        bool active = false;
        if (is_s) {
            if (lane == 0) {
                const int q = min(max(qi[b], 0), NS - 1);
                cand = q; active = true;
                if (qv[b] > 0) walk[bsel * NS + q] = 1.0f;
            } else if (lane < 13) {
                cand = e_stgt[bsel][lane - 1]; active = true;
            }
        } else {
            if (lane < 12) { cand = e_mtgt[bsel][lane]; active = true; }
        }
        const unsigned m = __match_any_sync(0xffffffffu, cand);
        const bool keep = active && ((m & ((1u << lane) - 1u)) == 0u);
        const unsigned keepmask = __ballot_sync(0xffffffffu, keep);
        if (keep) {
            const int idx = __popc(keepmask & ((1u << lane) - 1u));
            if (is_s) scand[bsel][idx] = cand; else vcand[bsel][idx] = cand;
        }
        if (lane == 0) {
            if (is_s) n_scand[bsel] = __popc(keepmask);
            else      n_vcand[bsel] = __popc(keepmask);
        }
    }
    // apply gates to edge values
    if (tid >= 128 && tid < 152) {
        const int u = tid - 128;
        const int bsel = u / NT, t = u % NT;
        e_mval[bsel][t] *= gate_s[0][bsel][t];
        e_sval[bsel][t] *= gate_s[1][bsel][t];
    }
    __syncthreads();

    // walk evolution: warp 0 = batch A, warp 1 = batch B
    if (tid < 64) {
        const int w = tid >> 5;
        const int lane = tid & 31;
        float* wk = walk + w * NS;
        float* nw = nwalk + w * NS;
        float* ws = wsum + w * NS;
        float* vv = vw + w * NS;
        const int nsc = n_scand[w];
        for (int iter = 0; iter <= GRAPH_STEPS; iter++) {
            if (lane < nsc) ws[scand[w][lane]] += wk[scand[w][lane]];
            if (lane < NT) {
                const float c = wk[e_msrc[w][lane]] * e_mval[w][lane];
                if (c != 0.f) atomicAdd(&vv[e_mtgt[w][lane]], c);
            }
            __syncwarp();
            if (iter < GRAPH_STEPS) {
                if (lane < nsc) nw[scand[w][lane]] = 0.f;
                __syncwarp();
                if (lane < NT) {
                    const float c = wk[e_msrc[w][lane]] * e_sval[w][lane];
                    if (c != 0.f) atomicAdd(&nw[e_stgt[w][lane]], c);
                }
                __syncwarp();
                if (lane < nsc) wk[scand[w][lane]] = nw[scand[w][lane]];
                __syncwarp();
            }
        }
    }
    __syncthreads();

    // sparse gather -> gs2[k] = (gsA[k], gsB[k])  (duplicated per ch)
    if (tid < 512) {
        float rA, rB;
        if (tid < 256) {
            const int d = tid;
            float a0 = 0.f, a1 = 0.f;
            const int n0 = n_scand[0], n1 = n_scand[1];
            for (int c = 0; c < n0; c++) {
                const int s = scand[0][c];
                a0 = fmaf(wsum[s], symbol_emb[s * ND + d], a0);
            }
            for (int c = 0; c < n1; c++) {
                const int s = scand[1][c];
                a1 = fmaf(wsum[NS + s], symbol_emb[s * ND + d], a1);
            }
            rA = a0; rB = a1;
        } else {
            const int d = tid - 256;
            float a0 = 0.f, a1 = 0.f;
            const int n0 = n_vcand[0], n1 = n_vcand[1];
            for (int c = 0; c < n0; c++) {
                const int v = vcand[0][c];
                a0 = fmaf(vw[v], value_emb[v * ND + d], a0);
            }
            for (int c = 0; c < n1; c++) {
                const int v = vcand[1][c];
                a1 = fmaf(vw[NS + v], value_emb[v * ND + d], a1);
            }
            rA = a0; rB = a1;
        }
        gs2[tid] = pk2(rA, rB);
    }
    __syncthreads();

    ull* comb = (ull*)ubuf;   // walk arrays dead; 2048 ull slots (16KB)

    // ---- layer 1: this block's 128-col half, full K=512 ----
    const float* __restrict__ W1 = br ? Wo1 : Wf1;
    const float* __restrict__ B1 = br ? bo1 : bf1;
    {
        const int cp = tid & 63;          // col pair within half
        const int kg = tid >> 6;          // 0..15, 32 k each
        const int j0 = ch * 128 + 2 * cp;
        ull a0 = 0ull, a1 = 0ull;
        const int k0 = kg * 32;
        #pragma unroll 8
        for (int kk = 0; kk < 32; kk++) {
            const int k = k0 + kk;
            const float2 w = *(const float2*)&W1[k * ND + j0];
            const ull av = gs2[k];
            a0 = fma2(av, pk2(w.x, w.x), a0);
            a1 = fma2(av, pk2(w.y, w.y), a1);
        }
        comb[(kg * 2 + 0) * 64 + cp] = a0;
        comb[(kg * 2 + 1) * 64 + cp] = a1;
    }
    __syncthreads();
    if (tid < 128) {
        const int cp = tid & 63, pay = tid >> 6;
        ull s = comb[(0 * 2 + pay) * 64 + cp];
        #pragma unroll
        for (int kg = 1; kg < 16; kg++)
            s = add2(s, comb[(kg * 2 + pay) * 64 + cp]);
        const int col = ch * 128 + 2 * cp + pay;
        const float2 f = upk(s);
        const float bb = B1[col];
        h2[2 * cp + pay] = pk2(gelu_f(f.x + bb), gelu_f(f.y + bb));
    }
    __syncthreads();

    // ---- layer 2: K = this block's 128 h entries, ALL output cols ----
    if (br) {
        // logits: 512 cols -> 256 col-pairs; kg = 4 x 32 k
        const int cp = tid & 255;
        const int kg = tid >> 8;
        const int kbase = ch * 128;
        ull a0 = 0ull, a1 = 0ull;
        const int k0 = kg * 32;
        #pragma unroll 8
        for (int kk = 0; kk < 32; kk++) {
            const int k = k0 + kk;
            const float2 w = *(const float2*)&Wo2[(kbase + k) * NV + 2 * cp];
            const ull av = h2[k];
            a0 = fma2(av, pk2(w.x, w.x), a0);
            a1 = fma2(av, pk2(w.y, w.y), a1);
        }
        comb[(kg * 2 + 0) * 256 + cp] = a0;
        comb[(kg * 2 + 1) * 256 + cp] = a1;
        __syncthreads();
        if (tid < 512) {
            const int cp2 = tid & 255, pay = tid >> 8;
            ull s = comb[(0 * 2 + pay) * 256 + cp2];
            #pragma unroll
            for (int kg2 = 1; kg2 < 4; kg2++)
                s = add2(s, comb[(kg2 * 2 + pay) * 256 + cp2]);
            const int col = 2 * cp2 + pay;
            float2 f = upk(s);
            if (ch == 0) { const float bb = bo2[col]; f.x += bb; f.y += bb; }
            atomicAdd(&out[bA * NV + col], f.x);
            atomicAdd(&out[(bA + 1) * NV + col], f.y);
        }
    } else {
        // feedback: 256 cols -> 128 col-pairs; kg = 8 x 16 k
        const int cp = tid & 127;
        const int kg = tid >> 7;
        const int kbase = ch * 128;
        ull a0 = 0ull, a1 = 0ull;
        const int k0 = kg * 16;
        #pragma unroll 8
        for (int kk = 0; kk < 16; kk++) {
            const int k = k0 + kk;
            const float2 w = *(const float2*)&Wf2[(kbase + k) * ND + 2 * cp];
            const ull av = h2[k];
            a0 = fma2(av, pk2(w.x, w.x), a0);
            a1 = fma2(av, pk2(w.y, w.y), a1);
        }
        comb[(kg * 2 + 0) * 128 + cp] = a0;
        comb[(kg * 2 + 1) * 128 + cp] = a1;
        __syncthreads();
        if (tid < 256) {
            const int cp2 = tid & 127, pay = tid >> 7;
            ull s = comb[(0 * 2 + pay) * 128 + cp2];
            #pragma unroll
            for (int kg2 = 1; kg2 < 8; kg2++)
                s = add2(s, comb[(kg2 * 2 + pay) * 128 + cp2]);
            const int col = 2 * cp2 + pay;
            float2 f = upk(s);
            if (ch == 0) { const float bb = bf2[col]; f.x += bb; f.y += bb; }
            atomicAdd(&out[NB * NV + bA * ND + col], f.x);
            atomicAdd(&out[NB * NV + (bA + 1) * ND + col], f.y);
        }
    }
}

// ---------------------------------------------------------------------------
extern "C" void kernel_launch(void* const* d_in, const int* in_sizes, int n_in,
                              void* d_out, int out_size)
{
    const int*   event_marker       = (const int*)  d_in[0];
    const int*   source_idx         = (const int*)  d_in[1];
    const int*   source_valid       = (const int*)  d_in[2];
    const int*   target_symbol_idx  = (const int*)  d_in[3];
    const int*   target_symbol_vld  = (const int*)  d_in[4];
    const int*   target_value_idx   = (const int*)  d_in[5];
    const int*   target_value_vld   = (const int*)  d_in[6];
    const int*   query_idx          = (const int*)  d_in[7];
    const int*   query_valid        = (const int*)  d_in[8];
    const float* evidence           = (const float*)d_in[9];
    const float* symbol_emb         = (const float*)d_in[10];
    const float* value_emb          = (const float*)d_in[11];
    const float* Wmg1 = (const float*)d_in[12];
    const float* bmg1 = (const float*)d_in[13];
    const float* Wmg2 = (const float*)d_in[14];
    const float* bmg2 = (const float*)d_in[15];
    const float* Wsg1 = (const float*)d_in[16];
    const float* bsg1 = (const float*)d_in[17];
    const float* Wsg2 = (const float*)d_in[18];
    const float* bsg2 = (const float*)d_in[19];
    const float* Wf1  = (const float*)d_in[20];
    const float* bf1  = (const float*)d_in[21];
    const float* Wf2  = (const float*)d_in[22];
    const float* bf2  = (const float*)d_in[23];
    const float* Wo1  = (const float*)d_in[24];
    const float* bo1  = (const float*)d_in[25];
    const float* Wo2  = (const float*)d_in[26];
    const float* bo2  = (const float*)d_in[27];

    float* out = (float*)d_out;

    const int smem_bytes = 8 * NT * 128 * (int)sizeof(ull);   // 96KB
    cudaFuncSetAttribute(k_gates, cudaFuncAttributeMaxDynamicSharedMemorySize,
                         smem_bytes);

    k_gates<<<128, 1024, smem_bytes>>>(evidence, Wmg1, bmg1, Wmg2,
                                       Wsg1, bsg1, Wsg2, out);
    k_graph_out<<<128, 1024>>>(event_marker, source_idx, source_valid,
                               target_symbol_idx, target_symbol_vld,
                               target_value_idx, target_value_vld,
                               query_idx, query_valid,
                               symbol_emb, value_emb,
                               bmg2, bsg2,
                               Wf1, bf1, Wf2, bf2,
                               Wo1, bo1, Wo2, bo2, out);
}